// round 4
// baseline (speedup 1.0000x reference)
#include <cuda_runtime.h>
#include <cstdint>

#define B 8
#define L 4096
#define F 64

#define TM 64            // i-rows per block (gemm)
#define TK 32            // j-chunk
#define NCHUNK (L / TK)  // 128
#define HS_STRIDE 34     // 32 + pad2 -> stride-2 bank pattern, 8B aligned rows

typedef unsigned long long ull;

// 8 MB scratch: hiddenT[b][o][j]  (o-major rows, j contiguous)
__device__ float g_hiddenT[(size_t)B * F * L];

__device__ __forceinline__ void cp16(void* dst, const void* src) {
    uint32_t d = (uint32_t)__cvta_generic_to_shared(dst);
    asm volatile("cp.async.cg.shared.global [%0], [%1], 16;" :: "r"(d), "l"(src));
}
__device__ __forceinline__ void cp8(void* dst, const void* src) {
    uint32_t d = (uint32_t)__cvta_generic_to_shared(dst);
    asm volatile("cp.async.ca.shared.global [%0], [%1], 8;" :: "r"(d), "l"(src));
}
__device__ __forceinline__ void cp_commit() {
    asm volatile("cp.async.commit_group;");
}
template <int N>
__device__ __forceinline__ void cp_wait() {
    asm volatile("cp.async.wait_group %0;" :: "n"(N));
}

__device__ __forceinline__ void fma2(ull& d, ull a, ull b) {
    asm("fma.rn.f32x2 %0, %1, %2, %0;" : "+l"(d) : "l"(a), "l"(b));
}
__device__ __forceinline__ float2 unpack2(ull v) {
    float2 f;
    asm("mov.b64 {%0, %1}, %2;" : "=f"(f.x), "=f"(f.y) : "l"(v));
    return f;
}

// ---------------------------------------------------------------------------
// Kernel 1: hiddenT[b][o][j] = sum_f text[b][j][f] * W[f][o]
// grid (L/64, B), 256 threads
// ---------------------------------------------------------------------------
__global__ __launch_bounds__(256) void hiddenT_kernel(
    const float* __restrict__ text, const float* __restrict__ W)
{
    __shared__ float w_s[F][F];      // 16 KB
    __shared__ float tb[64][65];     // text tile, later reused as transpose buffer

    const int tid  = threadIdx.x;
    const int b    = blockIdx.y;
    const int row0 = blockIdx.x * 64;

    // load W [64x64]
    for (int idx = tid; idx < F * F; idx += 256)
        w_s[idx >> 6][idx & 63] = W[idx];

    // load 64 text rows
    const float* tptr = text + ((size_t)b * L + row0) * F;
    for (int idx = tid; idx < 64 * F; idx += 256)
        tb[idx >> 6][idx & 63] = tptr[idx];
    __syncthreads();

    const int o  = tid & 63;
    const int ig = tid >> 6;   // 0..3, 16 rows each

    float acc[16];
#pragma unroll
    for (int r = 0; r < 16; ++r) {
        const int j = ig * 16 + r;
        float a = 0.f;
#pragma unroll
        for (int f = 0; f < F; ++f)
            a = fmaf(tb[j][f], w_s[f][o], a);
        acc[r] = a;
    }
    __syncthreads();   // all reads of tb done

    // transpose via smem: tb[o][j]
#pragma unroll
    for (int r = 0; r < 16; ++r)
        tb[o][ig * 16 + r] = acc[r];
    __syncthreads();

    // coalesced write: hiddenT rows (o-major, j contiguous)
    for (int idx = tid; idx < 64 * 64; idx += 256) {
        const int o2 = idx >> 6;
        const int jj = idx & 63;
        g_hiddenT[((size_t)b * F + o2) * L + row0 + jj] = tb[o2][jj];
    }
}

// ---------------------------------------------------------------------------
// Kernel 2: out[b][i][o] = sum_j adj[b][i][j] * hiddenT[b][o][j] + bias[o]
// grid (L/TM, B), 256 threads. FFMA2 with K-paired accumulators.
// Thread: o-lane ol (covers o=ol and o=ol+32), warp wg owns rows wg*8..wg*8+7.
// ---------------------------------------------------------------------------
__global__ __launch_bounds__(256) void gemm_kernel(
    const float* __restrict__ adj, const float* __restrict__ bias,
    float* __restrict__ out)
{
    __shared__ float as[2][TM][TK];            // 16 KB  (adj tiles)
    __shared__ float hs[2][F][HS_STRIDE];      // 17.4 KB (hiddenT tiles, padded)

    const int tid = threadIdx.x;
    const int ol  = tid & 31;   // o lane
    const int wg  = tid >> 5;   // warp id = row group (0..7)
    const int b   = blockIdx.y;
    const int i0  = blockIdx.x * TM;

    const float* adjBase = adj + ((size_t)b * L + i0) * L;
    const float* hTBase  = g_hiddenT + (size_t)b * F * L;

    ull acc0[8], acc1[8];
#pragma unroll
    for (int r = 0; r < 8; ++r) { acc0[r] = 0ULL; acc1[r] = 0ULL; }

    // ---- prefetch helper (inlined via lambda) ----
    auto prefetch = [&](int s, int jc) {
        const int j0 = jc * TK;
        // adj: 64 rows x 128B = 512 x 16B chunks, 2 per thread
#pragma unroll
        for (int k = 0; k < 2; ++k) {
            const int c   = tid + k * 256;
            const int row = c >> 3;
            const int cb  = c & 7;
            cp16(&as[s][row][cb * 4], adjBase + (size_t)row * L + j0 + cb * 4);
        }
        // hiddenT: 64 rows x 32 floats = 1024 x 8B chunks, 4 per thread
#pragma unroll
        for (int k = 0; k < 4; ++k) {
            const int c   = tid + k * 256;
            const int row = c >> 4;
            const int cb  = c & 15;
            cp8(&hs[s][row][cb * 2], hTBase + (size_t)row * L + j0 + cb * 2);
        }
        cp_commit();
    };

    prefetch(0, 0);

    for (int jc = 0; jc < NCHUNK; ++jc) {
        const int buf = jc & 1;
        if (jc + 1 < NCHUNK) {
            prefetch(buf ^ 1, jc + 1);
            cp_wait<1>();
        } else {
            cp_wait<0>();
        }
        __syncthreads();

        // compute on buf
#pragma unroll
        for (int jj = 0; jj < TK; jj += 8) {
            ull h0[4], h1[4];
#pragma unroll
            for (int u = 0; u < 4; ++u) {
                h0[u] = *(const ull*)&hs[buf][ol][jj + 2 * u];
                h1[u] = *(const ull*)&hs[buf][ol + 32][jj + 2 * u];
            }
#pragma unroll
            for (int r = 0; r < 8; ++r) {
                const float* arow = &as[buf][wg * 8 + r][jj];
                ulonglong2 aa = *(const ulonglong2*)arow;        // j..j+3 as 2 pairs
                ulonglong2 ab = *(const ulonglong2*)(arow + 4);  // j+4..j+7
                fma2(acc0[r], aa.x, h0[0]); fma2(acc0[r], aa.y, h0[1]);
                fma2(acc0[r], ab.x, h0[2]); fma2(acc0[r], ab.y, h0[3]);
                fma2(acc1[r], aa.x, h1[0]); fma2(acc1[r], aa.y, h1[1]);
                fma2(acc1[r], ab.x, h1[2]); fma2(acc1[r], ab.y, h1[3]);
            }
        }
        __syncthreads();
    }

    // epilogue: reduce pair, add bias, store
    const float b0 = bias[ol];
    const float b1 = bias[ol + 32];
#pragma unroll
    for (int r = 0; r < 8; ++r) {
        const size_t row = (size_t)b * L + i0 + wg * 8 + r;
        float2 v0 = unpack2(acc0[r]);
        float2 v1 = unpack2(acc1[r]);
        out[row * F + ol]      = v0.x + v0.y + b0;
        out[row * F + ol + 32] = v1.x + v1.y + b1;
    }
}

extern "C" void kernel_launch(void* const* d_in, const int* in_sizes, int n_in,
                              void* d_out, int out_size)
{
    const float* text = (const float*)d_in[0];
    const float* adj  = (const float*)d_in[1];
    const float* W    = (const float*)d_in[2];
    const float* bias = (const float*)d_in[3];
    float* out = (float*)d_out;

    hiddenT_kernel<<<dim3(L / 64, B), 256>>>(text, W);
    gemm_kernel<<<dim3(L / TM, B), 256>>>(adj, bias, out);
}

// round 12
// speedup vs baseline: 2.3631x; 2.3631x over previous
#include <cuda_runtime.h>
#include <cuda_bf16.h>
#include <cstdint>

#define B 8
#define L 4096
#define F 64
#define TM 128           // i-rows per CTA
#define KC 32            // j (K) chunk per stage
#define NC (L / KC)      // 128 chunks
#define AST 80           // smem row stride in bytes (40 bf16) for A and B tiles

// Scratch: hiddenT split into bf16 hi/lo, layout [b][o][j] (o-major, j contiguous)
__device__ __nv_bfloat16 g_hT_hi[(size_t)B * F * L];
__device__ __nv_bfloat16 g_hT_lo[(size_t)B * F * L];

// ---------------- smem map (bytes) ----------------
// A per stage per var: 128 rows * 80B = 10240;  B: 64 * 80 = 5120
#define A_HI_OFF(s) ((s) * 20480)
#define A_LO_OFF(s) ((s) * 20480 + 10240)
#define B_HI_OFF(s) (40960 + (s) * 10240)
#define B_LO_OFF(s) (40960 + (s) * 10240 + 5120)
#define BIAS_OFF    61440
#define SMEM_BYTES  61696

__device__ __forceinline__ uint32_t smem_u32(const void* p) {
    uint32_t a;
    asm("{ .reg .u64 t; cvta.to.shared.u64 t, %1; cvt.u32.u64 %0, t; }" : "=r"(a) : "l"(p));
    return a;
}
__device__ __forceinline__ void cp16(void* dst, const void* src) {
    uint32_t d = (uint32_t)__cvta_generic_to_shared(dst);
    asm volatile("cp.async.cg.shared.global [%0], [%1], 16;" :: "r"(d), "l"(src));
}
__device__ __forceinline__ void cp_commit() { asm volatile("cp.async.commit_group;"); }
template <int N> __device__ __forceinline__ void cp_wait() {
    asm volatile("cp.async.wait_group %0;" :: "n"(N));
}

__device__ __forceinline__ void ldsm4(uint32_t* r, uint32_t addr) {
    asm volatile("ldmatrix.sync.aligned.m8n8.x4.shared.b16 {%0,%1,%2,%3}, [%4];"
                 : "=r"(r[0]), "=r"(r[1]), "=r"(r[2]), "=r"(r[3]) : "r"(addr));
}
__device__ __forceinline__ void mma_bf16(float* c, const uint32_t* a, const uint32_t* b) {
    asm volatile(
        "mma.sync.aligned.m16n8k16.row.col.f32.bf16.bf16.f32 "
        "{%0,%1,%2,%3}, {%4,%5,%6,%7}, {%8,%9}, {%0,%1,%2,%3};"
        : "+f"(c[0]), "+f"(c[1]), "+f"(c[2]), "+f"(c[3])
        : "r"(a[0]), "r"(a[1]), "r"(a[2]), "r"(a[3]), "r"(b[0]), "r"(b[1]));
}

// ---------------------------------------------------------------------------
// Kernel 1: hiddenT[b][o][j] = sum_f text[b][j][f] * W[f][o], split to bf16 hi/lo
// ---------------------------------------------------------------------------
__global__ __launch_bounds__(256) void hiddenT_kernel(
    const float* __restrict__ text, const float* __restrict__ W)
{
    __shared__ float w_s[F][F];
    __shared__ float tb[64][65];

    const int tid  = threadIdx.x;
    const int b    = blockIdx.y;
    const int row0 = blockIdx.x * 64;

    for (int idx = tid; idx < F * F; idx += 256)
        w_s[idx >> 6][idx & 63] = W[idx];

    const float* tptr = text + ((size_t)b * L + row0) * F;
    for (int idx = tid; idx < 64 * F; idx += 256)
        tb[idx >> 6][idx & 63] = tptr[idx];
    __syncthreads();

    const int o  = tid & 63;
    const int ig = tid >> 6;

    float acc[16];
#pragma unroll
    for (int r = 0; r < 16; ++r) {
        const int j = ig * 16 + r;
        float a = 0.f;
#pragma unroll
        for (int f = 0; f < F; ++f)
            a = fmaf(tb[j][f], w_s[f][o], a);
        acc[r] = a;
    }
    __syncthreads();

#pragma unroll
    for (int r = 0; r < 16; ++r)
        tb[o][ig * 16 + r] = acc[r];
    __syncthreads();

    for (int idx = tid; idx < 64 * 64; idx += 256) {
        const int o2 = idx >> 6;
        const int jj = idx & 63;
        float v = tb[o2][jj];
        __nv_bfloat16 h = __float2bfloat16(v);
        __nv_bfloat16 l = __float2bfloat16(v - __bfloat162float(h));
        const size_t g = ((size_t)b * F + o2) * L + row0 + jj;
        g_hT_hi[g] = h;
        g_hT_lo[g] = l;
    }
}

// ---------------------------------------------------------------------------
// Kernel 2: warp-MMA GEMM (HMMA, base ISA — no tcgen05).
// out[b][i][o] = sum_j adj[b][i][j] * hiddenT[b][o][j] + bias[o]
// bf16 hi/lo 3-MMA emulation: Ah*Bh + Ah*Bl + Al*Bh, fp32 accumulate in regs.
// Warp w computes rows 16w..16w+15 x 64 cols (8 n-tiles of m16n8k16).
// ---------------------------------------------------------------------------
__global__ __launch_bounds__(256, 2) void gemm_mma_kernel(
    const float* __restrict__ adj, const float* __restrict__ bias,
    float* __restrict__ out)
{
    extern __shared__ __align__(1024) char sm[];
    const uint32_t smb = smem_u32(sm);
    const int tid  = threadIdx.x;
    const int w    = tid >> 5;
    const int lane = tid & 31;
    const int b    = blockIdx.y;
    const int i0   = blockIdx.x * TM;

    const float* adjBase = adj + ((size_t)b * L + i0) * L;
    const __nv_bfloat16* hHi = g_hT_hi + (size_t)b * F * L;
    const __nv_bfloat16* hLo = g_hT_lo + (size_t)b * F * L;

    if (tid < 64) ((float*)(sm + BIAS_OFF))[tid] = bias[tid];

    // ldmatrix lane-address components
    const uint32_t aRowOff  = (uint32_t)(w * 16 + (lane & 15)) * AST + (lane >> 4) * 16;
    const uint32_t bRowOff  = (uint32_t)((lane & 7) + ((lane >> 4) << 3)) * AST
                              + (((lane >> 3) & 1) << 4);

    float c[8][4];
#pragma unroll
    for (int n = 0; n < 8; ++n)
#pragma unroll
        for (int r = 0; r < 4; ++r) c[n][r] = 0.f;

    // loaders -------------------------------------------------------------
    auto issue_B = [&](int s, int jc) {
        const int j0  = jc * KC;
        const int row = tid >> 2;       // 0..63
        const int cb  = tid & 3;        // 4 x 16B per 64B row
        cp16(sm + B_HI_OFF(s) + row * AST + cb * 16, hHi + (size_t)row * L + j0 + cb * 8);
        cp16(sm + B_LO_OFF(s) + row * AST + cb * 16, hLo + (size_t)row * L + j0 + cb * 8);
        cp_commit();
    };
    auto ldg_A = [&](int jc, float4* v) {
        const int j0 = jc * KC;
#pragma unroll
        for (int k = 0; k < 4; ++k) {
            const int cidx = tid + k * 256;
            const int r = cidx >> 3;
            const int q = cidx & 7;
            v[k] = __ldcs(reinterpret_cast<const float4*>(adjBase + (size_t)r * L + j0 + q * 4));
        }
    };
    auto sts_A = [&](int s, const float4* v) {
#pragma unroll
        for (int k = 0; k < 4; ++k) {
            const int cidx = tid + k * 256;
            const int r = cidx >> 3;
            const int q = cidx & 7;
            float4 f = v[k];
            __nv_bfloat162 h01 = __floats2bfloat162_rn(f.x, f.y);
            __nv_bfloat162 h23 = __floats2bfloat162_rn(f.z, f.w);
            float2 g01 = __bfloat1622float2(h01);
            float2 g23 = __bfloat1622float2(h23);
            __nv_bfloat162 l01 = __floats2bfloat162_rn(f.x - g01.x, f.y - g01.y);
            __nv_bfloat162 l23 = __floats2bfloat162_rn(f.z - g23.x, f.w - g23.y);
            const uint32_t off = (uint32_t)r * AST + q * 8;
            *(uint2*)(sm + A_HI_OFF(s) + off) = make_uint2(*(uint32_t*)&h01, *(uint32_t*)&h23);
            *(uint2*)(sm + A_LO_OFF(s) + off) = make_uint2(*(uint32_t*)&l01, *(uint32_t*)&l23);
        }
    };

    // compute one stage (KC=32 -> two k16 steps) --------------------------
    auto compute = [&](int s) {
#pragma unroll
        for (int ks = 0; ks < 2; ++ks) {
            uint32_t ah[4], al[4], bh[16], bl[16];
            ldsm4(ah, smb + A_HI_OFF(s) + aRowOff + ks * 32);
            ldsm4(al, smb + A_LO_OFF(s) + aRowOff + ks * 32);
#pragma unroll
            for (int p = 0; p < 4; ++p) {
                ldsm4(bh + 4 * p, smb + B_HI_OFF(s) + bRowOff + p * (16 * AST) + ks * 32);
                ldsm4(bl + 4 * p, smb + B_LO_OFF(s) + bRowOff + p * (16 * AST) + ks * 32);
            }
#pragma unroll
            for (int n = 0; n < 8; ++n) {
                mma_bf16(c[n], ah, bh + 2 * n);
                mma_bf16(c[n], ah, bl + 2 * n);
                mma_bf16(c[n], al, bh + 2 * n);
            }
        }
    };

    // pipeline ------------------------------------------------------------
    {
        float4 v[4];
        issue_B(0, 0);
        ldg_A(0, v);
        sts_A(0, v);
        cp_wait<0>();
        __syncthreads();
    }

    for (int jc = 0; jc < NC; ++jc) {
        const int s = jc & 1;
        float4 v[4];
        const bool more = (jc + 1 < NC);
        if (more) {
            issue_B(s ^ 1, jc + 1);
            ldg_A(jc + 1, v);
        }
        compute(s);
        if (more) sts_A(s ^ 1, v);
        cp_wait<0>();
        __syncthreads();
    }

    // epilogue ------------------------------------------------------------
    const int gr = lane >> 2;        // 0..7
    const int q  = lane & 3;         // 0..3
    const float* sb = (const float*)(sm + BIAS_OFF);
    const int r0 = i0 + w * 16 + gr;
#pragma unroll
    for (int n = 0; n < 8; ++n) {
        const int col = n * 8 + 2 * q;
        const float bx = sb[col], by = sb[col + 1];
        float* p0 = out + ((size_t)b * L + r0) * F + col;
        float* p1 = out + ((size_t)b * L + r0 + 8) * F + col;
        *(float2*)p0 = make_float2(c[n][0] + bx, c[n][1] + by);
        *(float2*)p1 = make_float2(c[n][2] + bx, c[n][3] + by);
    }
}

extern "C" void kernel_launch(void* const* d_in, const int* in_sizes, int n_in,
                              void* d_out, int out_size)
{
    const float* text = (const float*)d_in[0];
    const float* adj  = (const float*)d_in[1];
    const float* W    = (const float*)d_in[2];
    const float* bias = (const float*)d_in[3];
    float* out = (float*)d_out;

    cudaFuncSetAttribute(gemm_mma_kernel,
                         cudaFuncAttributeMaxDynamicSharedMemorySize, SMEM_BYTES);

    hiddenT_kernel<<<dim3(L / 64, B), 256>>>(text, W);
    gemm_mma_kernel<<<dim3(L / TM, B), 256, SMEM_BYTES>>>(adj, bias, out);
}

// round 13
// speedup vs baseline: 2.4651x; 1.0432x over previous
#include <cuda_runtime.h>
#include <cuda_bf16.h>
#include <cstdint>

#define B 8
#define L 4096
#define F 64
#define TM 128           // i-rows per CTA
#define KC 32            // j (K) chunk per stage
#define NC (L / KC)      // 128 chunks
#define NSTAGE 3
#define AW 36            // smem row stride in words (32 + 4 pad) -> conflict-free
#define ROWB (AW * 4)    // 144 bytes per row

// Scratch: hiddenT as tf32-rounded fp32, layout [b][o][j] (o-major, j contiguous)
__device__ float g_hT[(size_t)B * F * L];

// ---------------- smem map (bytes) ----------------
// per stage: A = 128*144 = 18432, B = 64*144 = 9216 -> 27648
#define STAGE_BYTES 27648
#define A_OFF(s) ((s) * STAGE_BYTES)
#define B_OFF(s) ((s) * STAGE_BYTES + 18432)
#define BIAS_OFF (NSTAGE * STAGE_BYTES)
#define SMEM_BYTES (BIAS_OFF + 256)

__device__ __forceinline__ uint32_t smem_u32(const void* p) {
    uint32_t a;
    asm("{ .reg .u64 t; cvta.to.shared.u64 t, %1; cvt.u32.u64 %0, t; }" : "=r"(a) : "l"(p));
    return a;
}
__device__ __forceinline__ void cp16(uint32_t dst, const void* src) {
    asm volatile("cp.async.cg.shared.global [%0], [%1], 16;" :: "r"(dst), "l"(src));
}
__device__ __forceinline__ void cp_commit() { asm volatile("cp.async.commit_group;"); }
template <int N> __device__ __forceinline__ void cp_wait() {
    asm volatile("cp.async.wait_group %0;" :: "n"(N));
}
__device__ __forceinline__ uint32_t lds32(uint32_t addr) {
    uint32_t v;
    asm volatile("ld.shared.b32 %0, [%1];" : "=r"(v) : "r"(addr));
    return v;
}
__device__ __forceinline__ uint32_t f2tf32(float v) {
    uint32_t u;
    asm("cvt.rna.tf32.f32 %0, %1;" : "=r"(u) : "f"(v));
    return u;
}
__device__ __forceinline__ void mma_tf32(float* c, const uint32_t* a, uint32_t b0, uint32_t b1) {
    asm volatile(
        "mma.sync.aligned.m16n8k8.row.col.f32.tf32.tf32.f32 "
        "{%0,%1,%2,%3}, {%4,%5,%6,%7}, {%8,%9}, {%0,%1,%2,%3};"
        : "+f"(c[0]), "+f"(c[1]), "+f"(c[2]), "+f"(c[3])
        : "r"(a[0]), "r"(a[1]), "r"(a[2]), "r"(a[3]), "r"(b0), "r"(b1));
}

// ---------------------------------------------------------------------------
// Kernel 1: hiddenT[b][o][j] = tf32_round( sum_f text[b][j][f] * W[f][o] )
// ---------------------------------------------------------------------------
__global__ __launch_bounds__(256) void hiddenT_kernel(
    const float* __restrict__ text, const float* __restrict__ W)
{
    __shared__ float w_s[F][F];
    __shared__ float tb[64][65];

    const int tid  = threadIdx.x;
    const int b    = blockIdx.y;
    const int row0 = blockIdx.x * 64;

    for (int idx = tid; idx < F * F; idx += 256)
        w_s[idx >> 6][idx & 63] = W[idx];

    const float* tptr = text + ((size_t)b * L + row0) * F;
    for (int idx = tid; idx < 64 * F; idx += 256)
        tb[idx >> 6][idx & 63] = tptr[idx];
    __syncthreads();

    const int o  = tid & 63;
    const int ig = tid >> 6;

    float acc[16];
#pragma unroll
    for (int r = 0; r < 16; ++r) {
        const int j = ig * 16 + r;
        float a = 0.f;
#pragma unroll
        for (int f = 0; f < F; ++f)
            a = fmaf(tb[j][f], w_s[f][o], a);
        acc[r] = a;
    }
    __syncthreads();

#pragma unroll
    for (int r = 0; r < 16; ++r)
        tb[o][ig * 16 + r] = acc[r];
    __syncthreads();

    for (int idx = tid; idx < 64 * 64; idx += 256) {
        const int o2 = idx >> 6;
        const int jj = idx & 63;
        uint32_t t = f2tf32(tb[o2][jj]);
        g_hT[((size_t)b * F + o2) * L + row0 + jj] = __uint_as_float(t);
    }
}

// ---------------------------------------------------------------------------
// Kernel 2: TF32 warp-MMA GEMM, pure cp.async pipeline (no in-loop conversion)
// out[b][i][o] = sum_j adj[b][i][j] * hiddenT[b][o][j] + bias[o]
// A = adj [128 x 32] raw fp32 (HW truncates to tf32); B = hiddenT [64 x 32].
// Warp w: rows 16w..16w+15 x 64 cols; 8 n-tiles of m16n8k8, 4 k-steps/chunk.
// ---------------------------------------------------------------------------
__global__ __launch_bounds__(256, 2) void gemm_mma_kernel(
    const float* __restrict__ adj, const float* __restrict__ bias,
    float* __restrict__ out)
{
    extern __shared__ __align__(1024) char sm[];
    const uint32_t smb = smem_u32(sm);
    const int tid  = threadIdx.x;
    const int w    = tid >> 5;
    const int lane = tid & 31;
    const int gr   = lane >> 2;   // 0..7
    const int cq   = lane & 3;    // 0..3
    const int b    = blockIdx.y;
    const int i0   = blockIdx.x * TM;

    const float* adjBase = adj + ((size_t)b * L + i0) * L;
    const float* hT      = g_hT + (size_t)b * F * L;

    if (tid < 64) ((float*)(sm + BIAS_OFF))[tid] = bias[tid];

    float c[8][4];
#pragma unroll
    for (int n = 0; n < 8; ++n)
#pragma unroll
        for (int r = 0; r < 4; ++r) c[n][r] = 0.f;

    // per-chunk prefetch: A 1024 cp16 (4/thread), B 512 cp16 (2/thread)
    auto prefetch = [&](int s, int jc) {
        const int j0 = jc * KC;
#pragma unroll
        for (int k = 0; k < 4; ++k) {
            const int idx = tid + k * 256;
            const int r = idx >> 3;
            const int q = idx & 7;
            cp16(smb + A_OFF(s) + r * ROWB + q * 16, adjBase + (size_t)r * L + j0 + q * 4);
        }
#pragma unroll
        for (int k = 0; k < 2; ++k) {
            const int idx = tid + k * 256;
            const int r = idx >> 3;
            const int q = idx & 7;
            cp16(smb + B_OFF(s) + r * ROWB + q * 16, hT + (size_t)r * L + j0 + q * 4);
        }
        cp_commit();
    };

    // fragment base addresses (bytes)
    const uint32_t aBase = ((uint32_t)(w * 16 + gr) * AW + cq) * 4;   // + A_OFF(s)
    const uint32_t bBase = ((uint32_t)gr * AW + cq) * 4;              // + B_OFF(s)

    auto compute = [&](int s) {
        const uint32_t aS = smb + A_OFF(s) + aBase;
        const uint32_t bS = smb + B_OFF(s) + bBase;
#pragma unroll
        for (int ks = 0; ks < 4; ++ks) {
            uint32_t a[4];
            a[0] = lds32(aS + ks * 32);                 // (gr,      c)
            a[1] = lds32(aS + ks * 32 + 8 * ROWB);      // (gr+8,    c)
            a[2] = lds32(aS + ks * 32 + 16);            // (gr,    c+4)
            a[3] = lds32(aS + ks * 32 + 8 * ROWB + 16); // (gr+8,  c+4)
            uint32_t bb[16];
#pragma unroll
            for (int n = 0; n < 8; ++n) {
                bb[2 * n]     = lds32(bS + n * (8 * ROWB) + ks * 32);      // (k=c,   n)
                bb[2 * n + 1] = lds32(bS + n * (8 * ROWB) + ks * 32 + 16); // (k=c+4, n)
            }
#pragma unroll
            for (int n = 0; n < 8; ++n)
                mma_tf32(c[n], a, bb[2 * n], bb[2 * n + 1]);
        }
    };

    prefetch(0, 0);
    prefetch(1, 1);

    for (int jc = 0; jc < NC; ++jc) {
        const int s = jc % NSTAGE;
        if (jc < NC - 1) cp_wait<1>();
        else             cp_wait<0>();
        __syncthreads();
        if (jc + 2 < NC) prefetch((jc + 2) % NSTAGE, jc + 2);
        compute(s);
    }

    // epilogue
    const float* sb = (const float*)(sm + BIAS_OFF);
    const int r0 = i0 + w * 16 + gr;
#pragma unroll
    for (int n = 0; n < 8; ++n) {
        const int col = n * 8 + 2 * cq;
        const float bx = sb[col], by = sb[col + 1];
        float* p0 = out + ((size_t)b * L + r0) * F + col;
        float* p1 = out + ((size_t)b * L + r0 + 8) * F + col;
        *(float2*)p0 = make_float2(c[n][0] + bx, c[n][1] + by);
        *(float2*)p1 = make_float2(c[n][2] + bx, c[n][3] + by);
    }
}

extern "C" void kernel_launch(void* const* d_in, const int* in_sizes, int n_in,
                              void* d_out, int out_size)
{
    const float* text = (const float*)d_in[0];
    const float* adj  = (const float*)d_in[1];
    const float* W    = (const float*)d_in[2];
    const float* bias = (const float*)d_in[3];
    float* out = (float*)d_out;

    cudaFuncSetAttribute(gemm_mma_kernel,
                         cudaFuncAttributeMaxDynamicSharedMemorySize, SMEM_BYTES);

    hiddenT_kernel<<<dim3(L / 64, B), 256>>>(text, W);
    gemm_mma_kernel<<<dim3(L / TM, B), 256, SMEM_BYTES>>>(adj, bias, out);
}

// round 15
// speedup vs baseline: 2.9739x; 1.2064x over previous
#include <cuda_runtime.h>
#include <cuda_bf16.h>
#include <cstdint>

#define B 8
#define L 4096
#define F 64
#define TM 128           // i-rows per CTA
#define KC 32            // j (K) chunk per stage
#define NC (L / KC)      // 128 chunks
#define NSTAGE 4
#define AW 36            // smem row stride in words (32 + 4 pad) -> conflict-free
#define ROWB (AW * 4)    // 144 bytes per row

// Scratch: hiddenT as tf32-rounded fp32, layout [b][o][j] (o-major, j contiguous)
__device__ float g_hT[(size_t)B * F * L];

// ---------------- smem map (bytes) ----------------
// per stage: A = 128*144 = 18432, B = 64*144 = 9216 -> 27648
#define STAGE_BYTES 27648
#define A_OFF(s) ((s) * STAGE_BYTES)
#define B_OFF(s) ((s) * STAGE_BYTES + 18432)
#define BIAS_OFF (NSTAGE * STAGE_BYTES)
#define SMEM_BYTES (BIAS_OFF + 256)

__device__ __forceinline__ uint32_t smem_u32(const void* p) {
    uint32_t a;
    asm("{ .reg .u64 t; cvta.to.shared.u64 t, %1; cvt.u32.u64 %0, t; }" : "=r"(a) : "l"(p));
    return a;
}
__device__ __forceinline__ void cp16(uint32_t dst, const void* src) {
    asm volatile("cp.async.cg.shared.global [%0], [%1], 16;" :: "r"(dst), "l"(src));
}
__device__ __forceinline__ void cp_commit() { asm volatile("cp.async.commit_group;"); }
template <int N> __device__ __forceinline__ void cp_wait() {
    asm volatile("cp.async.wait_group %0;" :: "n"(N));
}
__device__ __forceinline__ void ldsm4(uint32_t* r, uint32_t addr) {
    asm volatile("ldmatrix.sync.aligned.m8n8.x4.shared.b16 {%0,%1,%2,%3}, [%4];"
                 : "=r"(r[0]), "=r"(r[1]), "=r"(r[2]), "=r"(r[3]) : "r"(addr));
}
__device__ __forceinline__ uint32_t f2tf32(float v) {
    uint32_t u;
    asm("cvt.rna.tf32.f32 %0, %1;" : "=r"(u) : "f"(v));
    return u;
}
__device__ __forceinline__ void mma_tf32(float* c, const uint32_t* a, uint32_t b0, uint32_t b1) {
    asm volatile(
        "mma.sync.aligned.m16n8k8.row.col.f32.tf32.tf32.f32 "
        "{%0,%1,%2,%3}, {%4,%5,%6,%7}, {%8,%9}, {%0,%1,%2,%3};"
        : "+f"(c[0]), "+f"(c[1]), "+f"(c[2]), "+f"(c[3])
        : "r"(a[0]), "r"(a[1]), "r"(a[2]), "r"(a[3]), "r"(b0), "r"(b1));
}

// ---------------------------------------------------------------------------
// Kernel 1: hiddenT[b][o][j] = tf32_round( sum_f text[b][j][f] * W[f][o] )
// ---------------------------------------------------------------------------
__global__ __launch_bounds__(256) void hiddenT_kernel(
    const float* __restrict__ text, const float* __restrict__ W)
{
    __shared__ float w_s[F][F];
    __shared__ float tb[64][65];

    const int tid  = threadIdx.x;
    const int b    = blockIdx.y;
    const int row0 = blockIdx.x * 64;

    for (int idx = tid; idx < F * F; idx += 256)
        w_s[idx >> 6][idx & 63] = W[idx];

    const float* tptr = text + ((size_t)b * L + row0) * F;
    for (int idx = tid; idx < 64 * F; idx += 256)
        tb[idx >> 6][idx & 63] = tptr[idx];
    __syncthreads();

    const int o  = tid & 63;
    const int ig = tid >> 6;

    float acc[16];
#pragma unroll
    for (int r = 0; r < 16; ++r) {
        const int j = ig * 16 + r;
        float a = 0.f;
#pragma unroll
        for (int f = 0; f < F; ++f)
            a = fmaf(tb[j][f], w_s[f][o], a);
        acc[r] = a;
    }
    __syncthreads();

#pragma unroll
    for (int r = 0; r < 16; ++r)
        tb[o][ig * 16 + r] = acc[r];
    __syncthreads();

    for (int idx = tid; idx < 64 * 64; idx += 256) {
        const int o2 = idx >> 6;
        const int jj = idx & 63;
        uint32_t t = f2tf32(tb[o2][jj]);
        g_hT[((size_t)b * F + o2) * L + row0 + jj] = __uint_as_float(t);
    }
}

// ---------------------------------------------------------------------------
// Kernel 2: TF32 warp-MMA GEMM, 32x64 warp tiles, ldmatrix fragments,
// 4-stage cp.async pipeline with wait_group<2>.
// out[b][i][o] = sum_j adj[b][i][j] * hiddenT[b][o][j] + bias[o]
// 128 threads = 4 warps; warp w owns rows 32w..32w+31 x all 64 cols.
// ---------------------------------------------------------------------------
__global__ __launch_bounds__(128, 2) void gemm_mma_kernel(
    const float* __restrict__ adj, const float* __restrict__ bias,
    float* __restrict__ out)
{
    extern __shared__ __align__(1024) char sm[];
    const uint32_t smb = smem_u32(sm);
    const int tid  = threadIdx.x;
    const int w    = tid >> 5;
    const int lane = tid & 31;
    const int gr   = lane >> 2;   // 0..7
    const int cq   = lane & 3;    // 0..3
    const int b    = blockIdx.y;
    const int i0   = blockIdx.x * TM;

    const float* adjBase = adj + ((size_t)b * L + i0) * L;
    const float* hT      = g_hT + (size_t)b * F * L;

    if (tid < 64) ((float*)(sm + BIAS_OFF))[tid] = bias[tid];

    float c[2][8][4];
#pragma unroll
    for (int mg = 0; mg < 2; ++mg)
#pragma unroll
        for (int n = 0; n < 8; ++n)
#pragma unroll
            for (int r = 0; r < 4; ++r) c[mg][n][r] = 0.f;

    // per-chunk prefetch: A 1024 cp16 (8/thread), B 512 cp16 (4/thread)
    auto prefetch = [&](int s, int jc) {
        const int j0 = jc * KC;
#pragma unroll
        for (int k = 0; k < 8; ++k) {
            const int idx = tid + k * 128;
            const int r = idx >> 3;
            const int q = idx & 7;
            cp16(smb + A_OFF(s) + r * ROWB + q * 16, adjBase + (size_t)r * L + j0 + q * 4);
        }
#pragma unroll
        for (int k = 0; k < 4; ++k) {
            const int idx = tid + k * 128;
            const int r = idx >> 3;
            const int q = idx & 7;
            cp16(smb + B_OFF(s) + r * ROWB + q * 16, hT + (size_t)r * L + j0 + q * 4);
        }
        cp_commit();
    };

    // ldmatrix lane address offsets (bytes, within tile)
    // A x4: matrices = (rows0-7,k0-3)(rows8-15,k0-3)(rows0-7,k4-7)(rows8-15,k4-7)
    const uint32_t aOff = (uint32_t)(w * 32 + (lane & 15)) * ROWB + ((lane >> 4) << 4);
    // B x4: matrices = (n0-7,k0-3)(n0-7,k4-7)(n8-15,k0-3)(n8-15,k4-7)
    const uint32_t bOff = (uint32_t)((lane & 7) + ((lane >> 4) << 3)) * ROWB
                          + (((lane >> 3) & 1) << 4);

    auto compute = [&](int s) {
        const uint32_t aS = smb + A_OFF(s) + aOff;
        const uint32_t bS = smb + B_OFF(s) + bOff;
#pragma unroll
        for (int ks = 0; ks < 4; ++ks) {
            uint32_t a[2][4];
            ldsm4(a[0], aS + ks * 32);
            ldsm4(a[1], aS + ks * 32 + 16 * ROWB);
#pragma unroll
            for (int p = 0; p < 4; ++p) {
                uint32_t bb[4];
                ldsm4(bb, bS + p * (16 * ROWB) + ks * 32);
#pragma unroll
                for (int mg = 0; mg < 2; ++mg) {
                    mma_tf32(c[mg][2 * p],     a[mg], bb[0], bb[1]);
                    mma_tf32(c[mg][2 * p + 1], a[mg], bb[2], bb[3]);
                }
            }
        }
    };

    prefetch(0, 0);
    prefetch(1, 1);
    prefetch(2, 2);

    for (int jc = 0; jc < NC; ++jc) {
        const int s = jc % NSTAGE;
        if (jc <= NC - 3)      cp_wait<2>();
        else if (jc == NC - 2) cp_wait<1>();
        else                   cp_wait<0>();
        __syncthreads();
        if (jc + 3 < NC) prefetch((jc + 3) % NSTAGE, jc + 3);
        compute(s);
    }

    // epilogue
    const float* sb = (const float*)(sm + BIAS_OFF);
#pragma unroll
    for (int mg = 0; mg < 2; ++mg) {
        const int r0 = i0 + w * 32 + mg * 16 + gr;
#pragma unroll
        for (int n = 0; n < 8; ++n) {
            const int col = n * 8 + 2 * cq;
            const float bx = sb[col], by = sb[col + 1];
            float* p0 = out + ((size_t)b * L + r0) * F + col;
            float* p1 = out + ((size_t)b * L + r0 + 8) * F + col;
            *(float2*)p0 = make_float2(c[mg][n][0] + bx, c[mg][n][1] + by);
            *(float2*)p1 = make_float2(c[mg][n][2] + bx, c[mg][n][3] + by);
        }
    }
}

extern "C" void kernel_launch(void* const* d_in, const int* in_sizes, int n_in,
                              void* d_out, int out_size)
{
    const float* text = (const float*)d_in[0];
    const float* adj  = (const float*)d_in[1];
    const float* W    = (const float*)d_in[2];
    const float* bias = (const float*)d_in[3];
    float* out = (float*)d_out;

    cudaFuncSetAttribute(gemm_mma_kernel,
                         cudaFuncAttributeMaxDynamicSharedMemorySize, SMEM_BYTES);

    hiddenT_kernel<<<dim3(L / 64, B), 256>>>(text, W);
    gemm_mma_kernel<<<dim3(L / TM, B), 128, SMEM_BYTES>>>(adj, bias, out);
}